// round 1
// baseline (speedup 1.0000x reference)
#include <cuda_runtime.h>
#include <math.h>

// Problem constants
#define SQ   4096
#define EMB  768
#define NH   12
#define HD   64
#define WIN  256

// Scratch (allocation-free rule: __device__ globals)
__device__ float g_q[NH * SQ * HD];
__device__ float g_k[NH * SQ * HD];
__device__ float g_v[NH * SQ * HD];

// ---------------------------------------------------------------------------
// QKV projection: C = hs @ Wm + bm, scattered head-major into g_q/g_k/g_v.
// grid = (EMB/64, SQ/64, 3), block = 256. BM=BN=64, BK=16, 4x4 micro-tiles.
// ---------------------------------------------------------------------------
__global__ __launch_bounds__(256, 2) void qkv_kernel(
    const float* __restrict__ hs,
    const float* __restrict__ Wq, const float* __restrict__ bq,
    const float* __restrict__ Wk, const float* __restrict__ bk,
    const float* __restrict__ Wv, const float* __restrict__ bv)
{
    const int z = blockIdx.z;
    const float* Wm = (z == 0) ? Wq : (z == 1) ? Wk : Wv;
    const float* bm = (z == 0) ? bq : (z == 1) ? bk : bv;
    float* dst = (z == 0) ? g_q : (z == 1) ? g_k : g_v;

    const int bn0 = blockIdx.x * 64;   // output column tile (== head * 64)
    const int bm0 = blockIdx.y * 64;   // output row tile

    __shared__ float As[16][68];   // A transposed: As[k][i]
    __shared__ float Bs[16][68];   // Bs[k][j]

    const int tid = threadIdx.x;
    const int ty = tid >> 4, tx = tid & 15;
    const int i0 = ty * 4, j0 = tx * 4;

    // load indices
    const int ai = tid >> 2;            // 0..63 (A row)
    const int ak = (tid & 3) * 4;       // k sub-group
    const int bkr = tid >> 4;           // 0..15 (B k-row)
    const int bj  = (tid & 15) * 4;     // B col group

    float acc[4][4] = {};

    for (int kk = 0; kk < EMB; kk += 16) {
        float4 a4 = *(const float4*)&hs[(bm0 + ai) * EMB + kk + ak];
        float4 b4 = *(const float4*)&Wm[(kk + bkr) * EMB + bn0 + bj];
        As[ak + 0][ai] = a4.x;
        As[ak + 1][ai] = a4.y;
        As[ak + 2][ai] = a4.z;
        As[ak + 3][ai] = a4.w;
        *(float4*)&Bs[bkr][bj] = b4;
        __syncthreads();

        #pragma unroll
        for (int k = 0; k < 16; k++) {
            float4 av = *(const float4*)&As[k][i0];
            float4 bv = *(const float4*)&Bs[k][j0];
            float a[4] = {av.x, av.y, av.z, av.w};
            float b[4] = {bv.x, bv.y, bv.z, bv.w};
            #pragma unroll
            for (int ii = 0; ii < 4; ii++)
                #pragma unroll
                for (int jj = 0; jj < 4; jj++)
                    acc[ii][jj] = fmaf(a[ii], b[jj], acc[ii][jj]);
        }
        __syncthreads();
    }

    const int h = bn0 >> 6;                  // head index (tile == one head)
    const float scl = (z == 0) ? 0.125f : 1.0f;  // 1/sqrt(64) for Q
    #pragma unroll
    for (int ii = 0; ii < 4; ii++) {
        const int i = bm0 + i0 + ii;
        #pragma unroll
        for (int jj = 0; jj < 4; jj++) {
            const int d = j0 + jj;
            float v = (acc[ii][jj] + bm[bn0 + d]) * scl;
            dst[((size_t)h * SQ + i) * HD + d] = v;
        }
    }
}

// ---------------------------------------------------------------------------
// Banded attention, flash-style online softmax.
// grid = (SQ/64, NH), block = 256. 9 aligned 64-key tiles per query tile.
// Dynamic smem: QsT, KsT, Vs, Pt (each [64][68]) + kmsk[64].
// ---------------------------------------------------------------------------
#define TPAD 68
#define ATT_SMEM_FLOATS (4 * 64 * TPAD + 64)

__global__ __launch_bounds__(256, 2) void attn_kernel(
    const float* __restrict__ amask,
    const unsigned char* __restrict__ qmask,
    float* __restrict__ out)
{
    extern __shared__ float smem[];
    float (*QsT)[TPAD] = (float(*)[TPAD])(smem);
    float (*KsT)[TPAD] = (float(*)[TPAD])(smem + 64 * TPAD);
    float (*Vs)[TPAD]  = (float(*)[TPAD])(smem + 2 * 64 * TPAD);
    float (*Pt)[TPAD]  = (float(*)[TPAD])(smem + 3 * 64 * TPAD);
    float* kmsk = smem + 4 * 64 * TPAD;

    const int h  = blockIdx.y;
    const int q0 = blockIdx.x * 64;

    const int tid = threadIdx.x;
    const int ty = tid >> 4, tx = tid & 15;
    const int i0 = ty * 4;        // query rows owned by this thread
    const int c0 = tx * 4;        // key cols (score phase) / head dims (PV phase)

    const int li = tid >> 2;      // 0..63: row index for tile loads
    const int lq = tid & 3;       // 0..3 : 16-float slab within the 64-dim row

    // Load Q tile transposed: QsT[d][i]
    {
        const float* qptr = &g_q[((size_t)h * SQ + q0 + li) * HD];
        #pragma unroll
        for (int c = 0; c < 4; c++) {
            float4 v = *(const float4*)&qptr[lq * 16 + c * 4];
            QsT[lq * 16 + c * 4 + 0][li] = v.x;
            QsT[lq * 16 + c * 4 + 1][li] = v.y;
            QsT[lq * 16 + c * 4 + 2][li] = v.z;
            QsT[lq * 16 + c * 4 + 3][li] = v.w;
        }
    }

    float m_i[4], l_i[4], O[4][4];
    #pragma unroll
    for (int ii = 0; ii < 4; ii++) {
        m_i[ii] = -1e30f;
        l_i[ii] = 0.0f;
        #pragma unroll
        for (int cc = 0; cc < 4; cc++) O[ii][cc] = 0.0f;
    }

    for (int t = 0; t < 9; t++) {
        const int jb = q0 - 256 + t * 64;      // aligned tile: fully in or out
        if (jb < 0 || jb >= SQ) continue;

        __syncthreads();   // prior iteration's reads of KsT/Vs/Pt done

        // Load K tile transposed, V tile natural, key mask
        {
            const float* kptr = &g_k[((size_t)h * SQ + jb + li) * HD];
            const float* vptr = &g_v[((size_t)h * SQ + jb + li) * HD];
            #pragma unroll
            for (int c = 0; c < 4; c++) {
                float4 kv = *(const float4*)&kptr[lq * 16 + c * 4];
                KsT[lq * 16 + c * 4 + 0][li] = kv.x;
                KsT[lq * 16 + c * 4 + 1][li] = kv.y;
                KsT[lq * 16 + c * 4 + 2][li] = kv.z;
                KsT[lq * 16 + c * 4 + 3][li] = kv.w;
                float4 vv = *(const float4*)&vptr[lq * 16 + c * 4];
                *(float4*)&Vs[li][lq * 16 + c * 4] = vv;
            }
            if (tid < 64)
                kmsk[tid] = (amask[jb + tid] != 0.0f) ? -1e8f : 0.0f;
        }
        __syncthreads();

        // Scores: s[i][j] = sum_d QsT[d][i] * KsT[d][j]
        float s[4][4] = {};
        #pragma unroll 16
        for (int d = 0; d < 64; d++) {
            float4 av = *(const float4*)&QsT[d][i0];
            float4 bv = *(const float4*)&KsT[d][c0];
            float a[4] = {av.x, av.y, av.z, av.w};
            float b[4] = {bv.x, bv.y, bv.z, bv.w};
            #pragma unroll
            for (int ii = 0; ii < 4; ii++)
                #pragma unroll
                for (int jj = 0; jj < 4; jj++)
                    s[ii][jj] = fmaf(a[ii], b[jj], s[ii][jj]);
        }

        // Band mask + key mask + online softmax (per-row, replicated over tx)
        #pragma unroll
        for (int ii = 0; ii < 4; ii++) {
            const int gi = q0 + i0 + ii;
            float rowm = -1e30f;
            #pragma unroll
            for (int jj = 0; jj < 4; jj++) {
                const int gj = jb + c0 + jj;
                const int diff = gi - gj;
                const bool valid = (diff <= WIN) && (diff >= -WIN);
                float sv = valid ? (s[ii][jj] + kmsk[c0 + jj]) : -1e30f;
                s[ii][jj] = sv;
                rowm = fmaxf(rowm, sv);
            }
            #pragma unroll
            for (int o = 8; o >= 1; o >>= 1)
                rowm = fmaxf(rowm, __shfl_xor_sync(0xffffffffu, rowm, o, 16));

            const float newm = fmaxf(m_i[ii], rowm);
            const float rescale = __expf(m_i[ii] - newm);
            m_i[ii] = newm;

            float rs = 0.0f;
            #pragma unroll
            for (int jj = 0; jj < 4; jj++) {
                float p = __expf(s[ii][jj] - newm);
                s[ii][jj] = p;
                rs += p;
            }
            #pragma unroll
            for (int o = 8; o >= 1; o >>= 1)
                rs += __shfl_xor_sync(0xffffffffu, rs, o, 16);

            l_i[ii] = l_i[ii] * rescale + rs;
            #pragma unroll
            for (int cc = 0; cc < 4; cc++) O[ii][cc] *= rescale;
        }

        // Write P transposed: Pt[j][i]
        #pragma unroll
        for (int jj = 0; jj < 4; jj++)
            #pragma unroll
            for (int ii = 0; ii < 4; ii++)
                Pt[c0 + jj][i0 + ii] = s[ii][jj];
        __syncthreads();

        // O[i][dd] += sum_j Pt[j][i] * Vs[j][dd]
        #pragma unroll 16
        for (int j = 0; j < 64; j++) {
            float4 av = *(const float4*)&Pt[j][i0];
            float4 bv = *(const float4*)&Vs[j][c0];
            float a[4] = {av.x, av.y, av.z, av.w};
            float b[4] = {bv.x, bv.y, bv.z, bv.w};
            #pragma unroll
            for (int ii = 0; ii < 4; ii++)
                #pragma unroll
                for (int cc = 0; cc < 4; cc++)
                    O[ii][cc] = fmaf(a[ii], b[cc], O[ii][cc]);
        }
    }

    // Epilogue: normalize, apply is_index_masked, write (S, E) output
    #pragma unroll
    for (int ii = 0; ii < 4; ii++) {
        const int gi = q0 + i0 + ii;
        const float inv = 1.0f / l_i[ii];
        const bool zm = (qmask[gi] != 0);
        #pragma unroll
        for (int cc = 0; cc < 4; cc++) {
            float v = zm ? 0.0f : O[ii][cc] * inv;
            out[(size_t)gi * EMB + h * HD + c0 + cc] = v;
        }
    }
}

// ---------------------------------------------------------------------------
// Launch
// ---------------------------------------------------------------------------
extern "C" void kernel_launch(void* const* d_in, const int* in_sizes, int n_in,
                              void* d_out, int out_size)
{
    const float* hs            = (const float*)d_in[0];
    const float* amask         = (const float*)d_in[1];
    const unsigned char* qmask = (const unsigned char*)d_in[2];
    const float* Wq = (const float*)d_in[3];
    const float* bq = (const float*)d_in[4];
    const float* Wk = (const float*)d_in[5];
    const float* bk = (const float*)d_in[6];
    const float* Wv = (const float*)d_in[7];
    const float* bv = (const float*)d_in[8];
    float* out = (float*)d_out;

    qkv_kernel<<<dim3(EMB / 64, SQ / 64, 3), 256>>>(hs, Wq, bq, Wk, bk, Wv, bv);

    const int smem_bytes = ATT_SMEM_FLOATS * (int)sizeof(float);
    cudaFuncSetAttribute(attn_kernel,
                         cudaFuncAttributeMaxDynamicSharedMemorySize, smem_bytes);
    attn_kernel<<<dim3(SQ / 64, NH), 256, smem_bytes>>>(amask, qmask, out);
}